// round 14
// baseline (speedup 1.0000x reference)
#include <cuda_runtime.h>
#include <cuda_fp16.h>
#include <stdint.h>
#include <math.h>

#define TOKENS 32768
#define CH     384
#define DFF    1536
#define NHEAD  12
#define HDIM   32

// ---------------- scratch ----------------------------------------------------
__device__ __half g_hwin[(size_t)TOKENS * CH];
__device__ __half g_qkv [(size_t)TOKENS * 3 * CH];
__device__ __half g_attn[(size_t)TOKENS * CH];
__device__ float  g_x1  [(size_t)TOKENS * CH];
__device__ __half g_h2  [(size_t)TOKENS * CH];
__device__ __half g_f1  [(size_t)TOKENS * DFF];
__device__ __half g_wq  [3 * CH * CH];
__device__ __half g_wp  [CH * CH];
__device__ __half g_w1  [DFF * CH];
__device__ __half g_w2  [CH * DFF];
__device__ __half g_bias[NHEAD * 256 * 256];   // precomputed rel-pos bias

// ---------------- fused fp32 -> fp16 weight conversion ----------------------
__global__ void __launch_bounds__(256) f2h4(const float* __restrict__ s0, __half* d0,
                                            const float* __restrict__ s1, __half* d1,
                                            const float* __restrict__ s2, __half* d2,
                                            const float* __restrict__ s3, __half* d3)
{
    int q = blockIdx.x * 256 + threadIdx.x;
    const float* s; __half* d; int off;
    if      (q < 110592)  { s = s0; d = d0; off = q; }
    else if (q < 147456)  { s = s1; d = d1; off = q - 110592; }
    else if (q < 294912)  { s = s2; d = d2; off = q - 147456; }
    else if (q < 442368)  { s = s3; d = d3; off = q - 294912; }
    else return;
    float4 v = ((const float4*)s)[off];
    __half2* o = (__half2*)(d + off * 4);
    o[0] = __floats2half2_rn(v.x, v.y);
    o[1] = __floats2half2_rn(v.z, v.w);
}

// ---------------- rel-pos bias precompute: bp[head][query][key] -------------
__global__ void __launch_bounds__(256) bias_pre(const float* __restrict__ rpb,
                                                __half* __restrict__ bp)
{
    int i = blockIdx.x * 256 + threadIdx.x;     // 786432 total
    int head = i >> 16, r = (i >> 8) & 255, c = i & 255;
    int fr = (r >> 6) * 225 + ((r >> 3) & 7) * 15 + (r & 7);
    int fc = (c >> 6) * 225 + ((c >> 3) & 7) * 15 + (c & 7);
    bp[i] = __float2half(rpb[(fr - fc + 787) * NHEAD + head]);
}

// ---------------- LayerNorm (+ optional shift & window partition), half out -
template<bool WIN>
__global__ void __launch_bounds__(256) ln_kernel(const float* __restrict__ x,
                                                 const float* __restrict__ w,
                                                 const float* __restrict__ bb,
                                                 __half* __restrict__ out)
{
    int gw   = (blockIdx.x * blockDim.x + threadIdx.x) >> 5;
    int lane = threadIdx.x & 31;
    size_t src;
    if (WIN) {
        int b_ = gw >> 8, n = gw & 255;
        int wd = b_ >> 6, wh = (b_ >> 3) & 7, ww = b_ & 7;
        int id = n >> 6,  ih = (n >> 3) & 7,  iw = n & 7;
        int sd = (wd * 4 + id + 2) & 7;
        int sh = (wh * 8 + ih + 4) & 63;
        int sw = (ww * 8 + iw + 4) & 63;
        src = (size_t)(((sd << 6) + sh) * 64 + sw) * CH;
    } else {
        src = (size_t)gw * CH;
    }
    const float4* xp = (const float4*)(x + src);
    float4 v0 = xp[lane], v1 = xp[lane + 32], v2 = xp[lane + 64];
    float s  = v0.x + v0.y + v0.z + v0.w + v1.x + v1.y + v1.z + v1.w
             + v2.x + v2.y + v2.z + v2.w;
    float s2 = v0.x*v0.x + v0.y*v0.y + v0.z*v0.z + v0.w*v0.w
             + v1.x*v1.x + v1.y*v1.y + v1.z*v1.z + v1.w*v1.w
             + v2.x*v2.x + v2.y*v2.y + v2.z*v2.z + v2.w*v2.w;
    #pragma unroll
    for (int o = 16; o; o >>= 1) {
        s  += __shfl_xor_sync(0xFFFFFFFFu, s,  o);
        s2 += __shfl_xor_sync(0xFFFFFFFFu, s2, o);
    }
    float mu  = s * (1.f / CH);
    float var = s2 * (1.f / CH) - mu * mu;
    float rsv = rsqrtf(var + 1e-5f);

    __half2* op = (__half2*)(out + (size_t)gw * CH);
    const float4* wp = (const float4*)w;
    const float4* bp = (const float4*)bb;
    float4 vv[3] = {v0, v1, v2};
    #pragma unroll
    for (int i = 0; i < 3; i++) {
        float4 wv = wp[lane + 32 * i];
        float4 bv = bp[lane + 32 * i];
        float rx = (vv[i].x - mu) * rsv * wv.x + bv.x;
        float ry = (vv[i].y - mu) * rsv * wv.y + bv.y;
        float rz = (vv[i].z - mu) * rsv * wv.z + bv.z;
        float rw = (vv[i].w - mu) * rsv * wv.w + bv.w;
        op[64 * i + 2 * lane]     = __floats2half2_rn(rx, ry);
        op[64 * i + 2 * lane + 1] = __floats2half2_rn(rz, rw);
    }
}

// windowed token -> spatial token (reverse shift + window reverse)
__device__ __forceinline__ int spatial_of(int t) {
    int b_ = t >> 8, n = t & 255;
    int A = (((b_ >> 6)       * 4) + (n >> 6)       + 2) & 7;
    int B = ((((b_ >> 3) & 7) * 8) + ((n >> 3) & 7) + 4) & 63;
    int Cc = (((b_ & 7)       * 8) + (n & 7)        + 4) & 63;
    return ((A << 6) + B) * 64 + Cc;
}

// ---------------- mma/ldmatrix macros ----------------------------------------
#define LDSM4(r0,r1,r2,r3,addr) \
    asm volatile("ldmatrix.sync.aligned.m8n8.x4.shared.b16 {%0,%1,%2,%3}, [%4];" \
        : "=r"(r0), "=r"(r1), "=r"(r2), "=r"(r3) : "r"(addr))

#define LDSM4T(r0,r1,r2,r3,addr) \
    asm volatile("ldmatrix.sync.aligned.m8n8.x4.trans.shared.b16 {%0,%1,%2,%3}, [%4];" \
        : "=r"(r0), "=r"(r1), "=r"(r2), "=r"(r3) : "r"(addr))

#define MMA16816(d,a0,a1,a2,a3,b0,b1) \
    asm volatile("mma.sync.aligned.m16n8k16.row.col.f32.f16.f16.f32 " \
        "{%0,%1,%2,%3}, {%4,%5,%6,%7}, {%8,%9}, {%0,%1,%2,%3};" \
        : "+f"(d[0]), "+f"(d[1]), "+f"(d[2]), "+f"(d[3]) \
        : "r"(a0), "r"(a1), "r"(a2), "r"(a3), "r"(b0), "r"(b1))

#define CPA16(dst, src) \
    asm volatile("cp.async.cg.shared.global [%0], [%1], 16;" :: "r"(dst), "l"(src))

// ---------------- fp16 tensor-core GEMM, 64x128 tile, 3 CTAs/SM -------------
// A: MxK half row-major, B: NxK half row-major. 64x128x32 tiles, 8 warps
// (2M x 4N, 32x32 per warp), 3-stage cp.async pipeline.
// EPI: 0 = none, 1 = exact GELU, 2 = += res, 3 = window-reverse scatter + res
#define LDT     40
#define STAGEH  (192 * LDT)          // halves per stage: A(64 rows) + B(128 rows)
#define STAGEB  (STAGEH * 2)         // bytes per stage = 15360
#define NSTAGE  3
#define SMEM_BYTES (NSTAGE * STAGEB) // 46080

__device__ __forceinline__ float gelu_f(float v) {
    return 0.5f * v * (1.f + erff(v * 0.70710678118654752f));
}

#define ISSUE(st, k0) do { \
    uint32_t d_ = smemBase + (uint32_t)(st) * STAGEB; \
    CPA16(d_ + offA0, Ap0 + (k0)); \
    CPA16(d_ + offB0, Bp0 + (k0)); \
    CPA16(d_ + offB1, Bp1 + (k0)); \
    asm volatile("cp.async.commit_group;"); \
} while (0)

template<int EPI, typename OutT>
__global__ void __launch_bounds__(256, 3) hgemm_nt(const __half* __restrict__ A,
                                                   const __half* __restrict__ B,
                                                   const float* __restrict__ bias,
                                                   const float* __restrict__ res,
                                                   OutT* __restrict__ Cout,
                                                   int M, int N, int K)
{
    extern __shared__ __half smp[];
    int tid  = threadIdx.x;
    int lane = tid & 31;
    int wid  = tid >> 5;
    int wm   = wid >> 2;          // 0..1  (M: 32-row slabs)
    int wn   = wid & 3;           // 0..3  (N: 32-col slabs)
    int m0 = blockIdx.y * 64, n0 = blockIdx.x * 128;

    int rg = tid >> 2, sg = tid & 3;
    const __half* Ap0 = A + (size_t)(m0 + rg) * K + sg * 8;          // 64 A rows
    const __half* Bp0 = B + (size_t)(n0 + rg) * K + sg * 8;          // B rows 0..63
    const __half* Bp1 = B + (size_t)(n0 + rg + 64) * K + sg * 8;     // B rows 64..127

    uint32_t smemBase = (uint32_t)__cvta_generic_to_shared(smp);
    uint32_t offA0 = (uint32_t)(rg * LDT + sg * 8) * 2;
    uint32_t offB0 = (uint32_t)((64 + rg) * LDT + sg * 8) * 2;
    uint32_t offB1 = (uint32_t)((128 + rg) * LDT + sg * 8) * 2;

    // ldmatrix per-lane byte addresses within stage 0
    uint32_t aB[2], bB[2];
    #pragma unroll
    for (int mt = 0; mt < 2; mt++)
        aB[mt] = smemBase +
            (uint32_t)((wm * 32 + mt * 16 + (lane & 15)) * LDT + (lane >> 4) * 8) * 2;
    #pragma unroll
    for (int nt2 = 0; nt2 < 2; nt2++)
        bB[nt2] = smemBase +
            (uint32_t)((64 + wn * 32 + nt2 * 16 + ((lane >> 3) & 1) * 8 + (lane & 7)) * LDT
                       + (lane >> 4) * 8) * 2;

    float acc[2][4][4];
    #pragma unroll
    for (int i = 0; i < 2; i++)
        #pragma unroll
        for (int j = 0; j < 4; j++)
            #pragma unroll
            for (int c = 0; c < 4; c++) acc[i][j][c] = 0.f;

    int NIT = K >> 5;
    ISSUE(0, 0);
    ISSUE(1, 32);

    int st = 0;
    for (int i = 0; i < NIT; i++) {
        if (i + 1 < NIT) asm volatile("cp.async.wait_group 1;");
        else             asm volatile("cp.async.wait_group 0;");
        __syncthreads();
        if (i + 2 < NIT) {
            int st2 = st + 2; if (st2 >= NSTAGE) st2 -= NSTAGE;
            ISSUE(st2, (i + 2) * 32);
        }
        uint32_t sb = (uint32_t)st * STAGEB;
        #pragma unroll
        for (int ks = 0; ks < 2; ks++) {
            uint32_t a[2][4], b[2][4];
            LDSM4(a[0][0], a[0][1], a[0][2], a[0][3], aB[0] + sb + ks * 32);
            LDSM4(a[1][0], a[1][1], a[1][2], a[1][3], aB[1] + sb + ks * 32);
            LDSM4(b[0][0], b[0][1], b[0][2], b[0][3], bB[0] + sb + ks * 32);
            LDSM4(b[1][0], b[1][1], b[1][2], b[1][3], bB[1] + sb + ks * 32);
            #pragma unroll
            for (int nt2 = 0; nt2 < 2; nt2++)
                #pragma unroll
                for (int mt = 0; mt < 2; mt++) {
                    MMA16816(acc[mt][nt2 * 2],     a[mt][0], a[mt][1], a[mt][2], a[mt][3],
                             b[nt2][0], b[nt2][2]);
                    MMA16816(acc[mt][nt2 * 2 + 1], a[mt][0], a[mt][1], a[mt][2], a[mt][3],
                             b[nt2][1], b[nt2][3]);
                }
        }
        st++; if (st == NSTAGE) st = 0;
    }

    // epilogue: warp covers rows m0+wm*32..+31, cols n0+wn*32..+31
    int qr = lane >> 2, qc = (lane & 3) * 2;
    #pragma unroll
    for (int nt = 0; nt < 4; nt++) {
        int col = n0 + wn * 32 + nt * 8 + qc;
        float b0 = bias[col], b1 = bias[col + 1];
        #pragma unroll
        for (int mt = 0; mt < 2; mt++) {
            int ra = m0 + wm * 32 + mt * 16 + qr;
            int rb = ra + 8;
            float v0 = acc[mt][nt][0] + b0, v1 = acc[mt][nt][1] + b1;
            float v2 = acc[mt][nt][2] + b0, v3 = acc[mt][nt][3] + b1;
            if (EPI == 1) {
                v0 = gelu_f(v0); v1 = gelu_f(v1);
                v2 = gelu_f(v2); v3 = gelu_f(v3);
            }
            if (EPI == 2) {
                const float2 ru = *(const float2*)(res + (size_t)ra * N + col);
                const float2 rl = *(const float2*)(res + (size_t)rb * N + col);
                v0 += ru.x; v1 += ru.y; v2 += rl.x; v3 += rl.y;
            }
            if (EPI == 3) {
                int sa = spatial_of(ra), sbr = spatial_of(rb);
                const float2 ru = *(const float2*)(res + (size_t)sa * N + col);
                const float2 rl = *(const float2*)(res + (size_t)sbr * N + col);
                v0 += ru.x; v1 += ru.y; v2 += rl.x; v3 += rl.y;
                *(float2*)((float*)Cout + (size_t)sa  * N + col) = make_float2(v0, v1);
                *(float2*)((float*)Cout + (size_t)sbr * N + col) = make_float2(v2, v3);
                continue;
            }
            if (sizeof(OutT) == 2) {
                *(__half2*)((__half*)Cout + (size_t)ra * N + col) = __floats2half2_rn(v0, v1);
                *(__half2*)((__half*)Cout + (size_t)rb * N + col) = __floats2half2_rn(v2, v3);
            } else {
                *(float2*)((float*)Cout + (size_t)ra * N + col) = make_float2(v0, v1);
                *(float2*)((float*)Cout + (size_t)rb * N + col) = make_float2(v2, v3);
            }
        }
    }
}

// ---------------- tensor-core windowed attention ----------------------------
// one CTA per (head, window); 8 warps x 32 query rows; direct exp (no max:
// LN'd inputs => s ~ N(0,1), overflow-free).
#define ATT_SMEM (3 * 256 * LDT * 2)

__global__ void __launch_bounds__(256) attn_mma(const __half* __restrict__ qkv,
                                                const __half* __restrict__ bp,
                                                __half* __restrict__ out)
{
    extern __shared__ __half asmem[];
    __half* Qs = asmem;
    __half* Ks = asmem + 256 * LDT;
    __half* Vs = asmem + 2 * 256 * LDT;
    __shared__ int rs[256];

    int tid = threadIdx.x, lane = tid & 31, w = tid >> 5;
    int head = blockIdx.x, b_ = blockIdx.y;

    // shift-mask region id for token tid
    {
        int md = tid >> 6, mh = (tid >> 3) & 7, mw = tid & 7;
        int wd = b_ >> 6, wh = (b_ >> 3) & 7, ww = b_ & 7;
        int dd = wd * 4 + md, hh = wh * 8 + mh, wp = ww * 8 + mw;
        rs[tid] = ((dd < 4) ? 0 : ((dd < 6) ? 1 : 2)) * 9
                + ((hh < 56) ? 0 : ((hh < 60) ? 1 : 2)) * 3
                + ((wp < 56) ? 0 : ((wp < 60) ? 1 : 2));
    }

    // stage Q (scaled), K, V : row `tid`
    {
        const __half* src = qkv + ((size_t)(b_ * 256 + tid) * (3 * CH) + head * HDIM);
        __half2 sc2 = __float2half2_rn(0.17677669529663687f);
        __half2 qbuf[16];
        #pragma unroll
        for (int c = 0; c < 4; c++)
            *(uint4*)&qbuf[c * 4] = *(const uint4*)(src + c * 8);
        #pragma unroll
        for (int i = 0; i < 16; i++) qbuf[i] = __hmul2(qbuf[i], sc2);
        #pragma unroll
        for (int c = 0; c < 4; c++) {
            *(uint4*)(Qs + tid * LDT + c * 8) = *(uint4*)&qbuf[c * 4];
            *(uint4*)(Ks + tid * LDT + c * 8) = *(const uint4*)(src + CH     + c * 8);
            *(uint4*)(Vs + tid * LDT + c * 8) = *(const uint4*)(src + 2 * CH + c * 8);
        }
    }
    __syncthreads();

    int qr = lane >> 2, qc = (lane & 3) * 2;
    int rsq[2][2];
    #pragma unroll
    for (int mt = 0; mt < 2; mt++) {
        int r = w * 32 + mt * 16 + qr;
        rsq[mt][0] = rs[r]; rsq[mt][1] = rs[r + 8];
    }

    uint32_t smb = (uint32_t)__cvta_generic_to_shared(asmem);
    uint32_t aQ[2];
    #pragma unroll
    for (int mt = 0; mt < 2; mt++)
        aQ[mt] = smb + (uint32_t)((w * 32 + mt * 16 + (lane & 15)) * LDT
                                  + (lane >> 4) * 8) * 2;
    int krow = ((lane >> 3) & 1) * 8 + (lane & 7);
    uint32_t kb0 = smb + (uint32_t)(256 * LDT + krow * LDT + (lane >> 4) * 8) * 2;
    uint32_t vb0 = smb + (uint32_t)(2 * 256 * LDT + krow * LDT) * 2 + (lane >> 4) * 16;

    float Oacc[2][4][4];
    #pragma unroll
    for (int mt = 0; mt < 2; mt++)
        #pragma unroll
        for (int n = 0; n < 4; n++)
            #pragma unroll
            for (int e = 0; e < 4; e++) Oacc[mt][n][e] = 0.f;
    float rsum[2][2] = {{0.f, 0.f}, {0.f, 0.f}};

    for (int cb = 0; cb < 4; cb++) {
        float S[2][8][4];
        #pragma unroll
        for (int mt = 0; mt < 2; mt++)
            #pragma unroll
            for (int n = 0; n < 8; n++)
                #pragma unroll
                for (int e = 0; e < 4; e++) S[mt][n][e] = 0.f;

        #pragma unroll
        for (int ks = 0; ks < 2; ks++) {
            uint32_t a[2][4];
            #pragma unroll
            for (int mt = 0; mt < 2; mt++)
                LDSM4(a[mt][0], a[mt][1], a[mt][2], a[mt][3], aQ[mt] + ks * 32);
            #pragma unroll
            for (int nt2 = 0; nt2 < 4; nt2++) {
                uint32_t b0, b1, b2, b3;
                LDSM4(b0, b1, b2, b3,
                      kb0 + (uint32_t)(cb * 64 + nt2 * 16) * (LDT * 2) + ks * 32);
                #pragma unroll
                for (int mt = 0; mt < 2; mt++) {
                    MMA16816(S[mt][nt2 * 2],     a[mt][0], a[mt][1], a[mt][2], a[mt][3], b0, b2);
                    MMA16816(S[mt][nt2 * 2 + 1], a[mt][0], a[mt][1], a[mt][2], a[mt][3], b1, b3);
                }
            }
        }

        // bias + mask + exp -> P fragments
        uint32_t P[2][8][2];
        #pragma unroll
        for (int mt = 0; mt < 2; mt++) {
            int row = w * 32 + mt * 16 + qr;
            #pragma unroll
            for (int nt = 0; nt < 8; nt++) {
                int col = cb * 64 + nt * 8 + qc;
                float2 bU = __half22float2(*(const __half2*)(bp + ((head * 256 + row)     * 256 + col)));
                float2 bL = __half22float2(*(const __half2*)(bp + ((head * 256 + row + 8) * 256 + col)));
                int2 rcc = *(const int2*)(rs + col);
                float s0 = S[mt][nt][0] + bU.x + ((rcc.x == rsq[mt][0]) ? 0.f : -100.f);
                float s1 = S[mt][nt][1] + bU.y + ((rcc.y == rsq[mt][0]) ? 0.f : -100.f);
                float s2 = S[mt][nt][2] + bL.x + ((rcc.x == rsq[mt][1]) ? 0.f : -100.f);
                float s3 = S[mt][nt][3] + bL.y + ((rcc.y == rsq[mt][1]) ? 0.f : -100.f);
                float p0 = __expf(s0), p1 = __expf(s1);
                float p2 = __expf(s2), p3 = __expf(s3);
                rsum[mt][0] += p0 + p1;
                rsum[mt][1] += p2 + p3;
                __half2 h0 = __floats2half2_rn(p0, p1);
                __half2 h1 = __floats2half2_rn(p2, p3);
                P[mt][nt][0] = *(uint32_t*)&h0;
                P[mt][nt][1] = *(uint32_t*)&h1;
            }
        }

        // O += P @ V
        #pragma unroll
        for (int j = 0; j < 4; j++) {
            #pragma unroll
            for (int dh = 0; dh < 2; dh++) {
                uint32_t b0, b1, b2, b3;
                LDSM4T(b0, b1, b2, b3,
                       vb0 + (uint32_t)(cb * 64 + j * 16) * (LDT * 2) + dh * 32);
                #pragma unroll
                for (int mt = 0; mt < 2; mt++) {
                    MMA16816(Oacc[mt][dh * 2],
                             P[mt][2 * j][0], P[mt][2 * j][1],
                             P[mt][2 * j + 1][0], P[mt][2 * j + 1][1], b0, b1);
                    MMA16816(Oacc[mt][dh * 2 + 1],
                             P[mt][2 * j][0], P[mt][2 * j][1],
                             P[mt][2 * j + 1][0], P[mt][2 * j + 1][1], b2, b3);
                }
            }
        }
    }

    // row sums across quad, normalize, store
    float inv[2][2];
    #pragma unroll
    for (int mt = 0; mt < 2; mt++)
        #pragma unroll
        for (int h = 0; h < 2; h++) {
            float v = rsum[mt][h];
            v += __shfl_xor_sync(0xFFFFFFFFu, v, 1);
            v += __shfl_xor_sync(0xFFFFFFFFu, v, 2);
            inv[mt][h] = 1.f / v;
        }
    #pragma unroll
    for (int mt = 0; mt < 2; mt++) {
        int row = b_ * 256 + w * 32 + mt * 16 + qr;
        #pragma unroll
        for (int nd = 0; nd < 4; nd++) {
            int col = head * HDIM + nd * 8 + qc;
            __half2 h0 = __floats2half2_rn(Oacc[mt][nd][0] * inv[mt][0],
                                           Oacc[mt][nd][1] * inv[mt][0]);
            __half2 h1 = __floats2half2_rn(Oacc[mt][nd][2] * inv[mt][1],
                                           Oacc[mt][nd][3] * inv[mt][1]);
            *(__half2*)(out + (size_t)row * CH + col)       = h0;
            *(__half2*)(out + (size_t)(row + 8) * CH + col) = h1;
        }
    }
}

// ---------------- launch ----------------------------------------------------
extern "C" void kernel_launch(void* const* d_in, const int* in_sizes, int n_in,
                              void* d_out, int out_size)
{
    const float* x    = (const float*)d_in[0];
    const float* n1w  = (const float*)d_in[1];
    const float* n1b  = (const float*)d_in[2];
    const float* qkvw = (const float*)d_in[3];
    const float* qkvb = (const float*)d_in[4];
    const float* rpb  = (const float*)d_in[5];
    const float* pw   = (const float*)d_in[6];
    const float* pb   = (const float*)d_in[7];
    const float* n2w  = (const float*)d_in[8];
    const float* n2b  = (const float*)d_in[9];
    const float* f1w  = (const float*)d_in[10];
    const float* f1b  = (const float*)d_in[11];
    const float* f2w  = (const float*)d_in[12];
    const float* f2b  = (const float*)d_in[13];
    float* out = (float*)d_out;

    void *pv;
    __half *hwin, *qkv, *attn, *h2, *f1, *wq, *wpw, *w1, *w2, *bp;
    float *x1;
    cudaGetSymbolAddress(&pv, g_hwin); hwin = (__half*)pv;
    cudaGetSymbolAddress(&pv, g_qkv);  qkv  = (__half*)pv;
    cudaGetSymbolAddress(&pv, g_attn); attn = (__half*)pv;
    cudaGetSymbolAddress(&pv, g_x1);   x1   = (float*)pv;
    cudaGetSymbolAddress(&pv, g_h2);   h2   = (__half*)pv;
    cudaGetSymbolAddress(&pv, g_f1);   f1   = (__half*)pv;
    cudaGetSymbolAddress(&pv, g_wq);   wq   = (__half*)pv;
    cudaGetSymbolAddress(&pv, g_wp);   wpw  = (__half*)pv;
    cudaGetSymbolAddress(&pv, g_w1);   w1   = (__half*)pv;
    cudaGetSymbolAddress(&pv, g_w2);   w2   = (__half*)pv;
    cudaGetSymbolAddress(&pv, g_bias); bp   = (__half*)pv;

    cudaFuncSetAttribute(attn_mma,
                         cudaFuncAttributeMaxDynamicSharedMemorySize, ATT_SMEM);
    cudaFuncSetAttribute(hgemm_nt<0, __half>,
                         cudaFuncAttributeMaxDynamicSharedMemorySize, SMEM_BYTES);
    cudaFuncSetAttribute(hgemm_nt<1, __half>,
                         cudaFuncAttributeMaxDynamicSharedMemorySize, SMEM_BYTES);
    cudaFuncSetAttribute(hgemm_nt<2, float>,
                         cudaFuncAttributeMaxDynamicSharedMemorySize, SMEM_BYTES);
    cudaFuncSetAttribute(hgemm_nt<3, float>,
                         cudaFuncAttributeMaxDynamicSharedMemorySize, SMEM_BYTES);

    // 0. weight conversion + bias precompute
    f2h4<<<(442368 + 255) / 256, 256>>>(qkvw, wq, pw, wpw, f1w, w1, f2w, w2);
    bias_pre<<<NHEAD * 256 * 256 / 256, 256>>>(rpb, bp);

    // 1. LN1 + shift + window partition (half out)
    ln_kernel<true><<<TOKENS / 8, 256>>>(x, n1w, n1b, hwin);
    // 2. QKV (half out)
    hgemm_nt<0, __half><<<dim3(3*CH/128, TOKENS/64), 256, SMEM_BYTES>>>(
        hwin, wq, qkvb, nullptr, qkv, TOKENS, 3*CH, CH);
    // 3. attention (tensor-core, half out)
    attn_mma<<<dim3(NHEAD, 128), 256, ATT_SMEM>>>(qkv, bp, attn);
    // 4. proj + window-reverse + unshift + residual -> x1 (float)
    hgemm_nt<3, float><<<dim3(CH/128, TOKENS/64), 256, SMEM_BYTES>>>(
        attn, wpw, pb, x, x1, TOKENS, CH, CH);
    // 5. LN2 (half out)
    ln_kernel<false><<<TOKENS / 8, 256>>>(x1, n2w, n2b, h2);
    // 6. fc1 + GELU (half out)
    hgemm_nt<1, __half><<<dim3(DFF/128, TOKENS/64), 256, SMEM_BYTES>>>(
        h2, w1, f1b, nullptr, f1, TOKENS, DFF, CH);
    // 7. fc2 + residual -> d_out (fp32)
    hgemm_nt<2, float><<<dim3(CH/128, TOKENS/64), 256, SMEM_BYTES>>>(
        f1, w2, f2b, x1, out, TOKENS, CH, DFF);
}

// round 15
// speedup vs baseline: 1.0461x; 1.0461x over previous
#include <cuda_runtime.h>
#include <cuda_fp16.h>
#include <stdint.h>
#include <math.h>

#define TOKENS 32768
#define CH     384
#define DFF    1536
#define NHEAD  12
#define HDIM   32

// ---------------- scratch ----------------------------------------------------
__device__ __half g_hwin[(size_t)TOKENS * CH];
__device__ __half g_qkv [(size_t)TOKENS * 3 * CH];
__device__ __half g_attn[(size_t)TOKENS * CH];
__device__ float  g_x1  [(size_t)TOKENS * CH];
__device__ __half g_h2  [(size_t)TOKENS * CH];
__device__ __half g_f1  [(size_t)TOKENS * DFF];
__device__ __half g_wq  [3 * CH * CH];
__device__ __half g_wp  [CH * CH];
__device__ __half g_w1  [DFF * CH];
__device__ __half g_w2  [CH * DFF];
__device__ __half g_bias[NHEAD * 256 * 256];   // precomputed rel-pos bias

// ---------------- fused fp32 -> fp16 weight conversion ----------------------
__global__ void __launch_bounds__(256) f2h4(const float* __restrict__ s0, __half* d0,
                                            const float* __restrict__ s1, __half* d1,
                                            const float* __restrict__ s2, __half* d2,
                                            const float* __restrict__ s3, __half* d3)
{
    int q = blockIdx.x * 256 + threadIdx.x;
    const float* s; __half* d; int off;
    if      (q < 110592)  { s = s0; d = d0; off = q; }
    else if (q < 147456)  { s = s1; d = d1; off = q - 110592; }
    else if (q < 294912)  { s = s2; d = d2; off = q - 147456; }
    else if (q < 442368)  { s = s3; d = d3; off = q - 294912; }
    else return;
    float4 v = ((const float4*)s)[off];
    __half2* o = (__half2*)(d + off * 4);
    o[0] = __floats2half2_rn(v.x, v.y);
    o[1] = __floats2half2_rn(v.z, v.w);
}

// ---------------- rel-pos bias precompute: bp[head][query][key] -------------
__global__ void __launch_bounds__(256) bias_pre(const float* __restrict__ rpb,
                                                __half* __restrict__ bp)
{
    int i = blockIdx.x * 256 + threadIdx.x;     // 786432 total
    int head = i >> 16, r = (i >> 8) & 255, c = i & 255;
    int fr = (r >> 6) * 225 + ((r >> 3) & 7) * 15 + (r & 7);
    int fc = (c >> 6) * 225 + ((c >> 3) & 7) * 15 + (c & 7);
    bp[i] = __float2half(rpb[(fr - fc + 787) * NHEAD + head]);
}

// ---------------- LayerNorm (+ optional shift & window partition), half out -
template<bool WIN>
__global__ void __launch_bounds__(256) ln_kernel(const float* __restrict__ x,
                                                 const float* __restrict__ w,
                                                 const float* __restrict__ bb,
                                                 __half* __restrict__ out)
{
    int gw   = (blockIdx.x * blockDim.x + threadIdx.x) >> 5;
    int lane = threadIdx.x & 31;
    size_t src;
    if (WIN) {
        int b_ = gw >> 8, n = gw & 255;
        int wd = b_ >> 6, wh = (b_ >> 3) & 7, ww = b_ & 7;
        int id = n >> 6,  ih = (n >> 3) & 7,  iw = n & 7;
        int sd = (wd * 4 + id + 2) & 7;
        int sh = (wh * 8 + ih + 4) & 63;
        int sw = (ww * 8 + iw + 4) & 63;
        src = (size_t)(((sd << 6) + sh) * 64 + sw) * CH;
    } else {
        src = (size_t)gw * CH;
    }
    const float4* xp = (const float4*)(x + src);
    float4 v0 = xp[lane], v1 = xp[lane + 32], v2 = xp[lane + 64];
    float s  = v0.x + v0.y + v0.z + v0.w + v1.x + v1.y + v1.z + v1.w
             + v2.x + v2.y + v2.z + v2.w;
    float s2 = v0.x*v0.x + v0.y*v0.y + v0.z*v0.z + v0.w*v0.w
             + v1.x*v1.x + v1.y*v1.y + v1.z*v1.z + v1.w*v1.w
             + v2.x*v2.x + v2.y*v2.y + v2.z*v2.z + v2.w*v2.w;
    #pragma unroll
    for (int o = 16; o; o >>= 1) {
        s  += __shfl_xor_sync(0xFFFFFFFFu, s,  o);
        s2 += __shfl_xor_sync(0xFFFFFFFFu, s2, o);
    }
    float mu  = s * (1.f / CH);
    float var = s2 * (1.f / CH) - mu * mu;
    float rsv = rsqrtf(var + 1e-5f);

    __half2* op = (__half2*)(out + (size_t)gw * CH);
    const float4* wp = (const float4*)w;
    const float4* bp = (const float4*)bb;
    float4 vv[3] = {v0, v1, v2};
    #pragma unroll
    for (int i = 0; i < 3; i++) {
        float4 wv = wp[lane + 32 * i];
        float4 bv = bp[lane + 32 * i];
        float rx = (vv[i].x - mu) * rsv * wv.x + bv.x;
        float ry = (vv[i].y - mu) * rsv * wv.y + bv.y;
        float rz = (vv[i].z - mu) * rsv * wv.z + bv.z;
        float rw = (vv[i].w - mu) * rsv * wv.w + bv.w;
        op[64 * i + 2 * lane]     = __floats2half2_rn(rx, ry);
        op[64 * i + 2 * lane + 1] = __floats2half2_rn(rz, rw);
    }
}

// windowed token -> spatial token (reverse shift + window reverse)
__device__ __forceinline__ int spatial_of(int t) {
    int b_ = t >> 8, n = t & 255;
    int A = (((b_ >> 6)       * 4) + (n >> 6)       + 2) & 7;
    int B = ((((b_ >> 3) & 7) * 8) + ((n >> 3) & 7) + 4) & 63;
    int Cc = (((b_ & 7)       * 8) + (n & 7)        + 4) & 63;
    return ((A << 6) + B) * 64 + Cc;
}

// ---------------- mma/ldmatrix macros ----------------------------------------
#define LDSM4(r0,r1,r2,r3,addr) \
    asm volatile("ldmatrix.sync.aligned.m8n8.x4.shared.b16 {%0,%1,%2,%3}, [%4];" \
        : "=r"(r0), "=r"(r1), "=r"(r2), "=r"(r3) : "r"(addr))

#define LDSM4T(r0,r1,r2,r3,addr) \
    asm volatile("ldmatrix.sync.aligned.m8n8.x4.trans.shared.b16 {%0,%1,%2,%3}, [%4];" \
        : "=r"(r0), "=r"(r1), "=r"(r2), "=r"(r3) : "r"(addr))

#define MMA16816(d,a0,a1,a2,a3,b0,b1) \
    asm volatile("mma.sync.aligned.m16n8k16.row.col.f32.f16.f16.f32 " \
        "{%0,%1,%2,%3}, {%4,%5,%6,%7}, {%8,%9}, {%0,%1,%2,%3};" \
        : "+f"(d[0]), "+f"(d[1]), "+f"(d[2]), "+f"(d[3]) \
        : "r"(a0), "r"(a1), "r"(a2), "r"(a3), "r"(b0), "r"(b1))

#define CPA16(dst, src) \
    asm volatile("cp.async.cg.shared.global [%0], [%1], 16;" :: "r"(dst), "l"(src))

// ---------------- fp16 tensor-core GEMM, K-chunk 64, 2-stage pipeline -------
// A: MxK half row-major, B: NxK half row-major. 128x128 tile, 8 warps.
// Each stage holds TWO 32-k sub-tiles (A+B each); one barrier per 64-k chunk.
// EPI: 0 = none, 1 = exact GELU, 2 = += res, 3 = window-reverse scatter + res
#define LDT     40
#define STAGEH  (128 * LDT)
#define SUBB    (STAGEH * 2 * 2)     // bytes per 32-k sub-tile (A+B) = 20480
#define CHUNKB  (2 * SUBB)           // bytes per 64-k stage = 40960
#define NSTAGE  2
#define SMEM_BYTES (NSTAGE * CHUNKB) // 81920

__device__ __forceinline__ float gelu_f(float v) {
    return 0.5f * v * (1.f + erff(v * 0.70710678118654752f));
}

// issue one 64-k chunk (both sub-tiles) into stage st
#define ISSUE(st, k0) do { \
    uint32_t d_ = smemBase + (uint32_t)(st) * CHUNKB; \
    CPA16(d_ + offA0,        Ap0 + (k0)); \
    CPA16(d_ + offA1,        Ap1 + (k0)); \
    CPA16(d_ + offB0,        Bp0 + (k0)); \
    CPA16(d_ + offB1,        Bp1 + (k0)); \
    CPA16(d_ + SUBB + offA0, Ap0 + (k0) + 32); \
    CPA16(d_ + SUBB + offA1, Ap1 + (k0) + 32); \
    CPA16(d_ + SUBB + offB0, Bp0 + (k0) + 32); \
    CPA16(d_ + SUBB + offB1, Bp1 + (k0) + 32); \
    asm volatile("cp.async.commit_group;"); \
} while (0)

template<int EPI, typename OutT>
__global__ void __launch_bounds__(256) hgemm_nt(const __half* __restrict__ A,
                                                const __half* __restrict__ B,
                                                const float* __restrict__ bias,
                                                const float* __restrict__ res,
                                                OutT* __restrict__ Cout,
                                                int M, int N, int K)
{
    extern __shared__ __half smp[];
    int tid  = threadIdx.x;
    int lane = tid & 31;
    int wid  = tid >> 5;
    int wm   = wid & 3;
    int wn   = wid >> 2;
    int m0 = blockIdx.y * 128, n0 = blockIdx.x * 128;

    int r0g = tid >> 2, s0g = tid & 3;
    int r1g = (tid + 256) >> 2;
    const __half* Ap0 = A + (size_t)(m0 + r0g) * K + s0g * 8;
    const __half* Ap1 = A + (size_t)(m0 + r1g) * K + s0g * 8;
    const __half* Bp0 = B + (size_t)(n0 + r0g) * K + s0g * 8;
    const __half* Bp1 = B + (size_t)(n0 + r1g) * K + s0g * 8;

    uint32_t smemBase = (uint32_t)__cvta_generic_to_shared(smp);
    uint32_t offA0 = (uint32_t)(r0g * LDT + s0g * 8) * 2;
    uint32_t offA1 = (uint32_t)(r1g * LDT + s0g * 8) * 2;
    uint32_t offB0 = (uint32_t)(STAGEH + r0g * LDT + s0g * 8) * 2;
    uint32_t offB1 = (uint32_t)(STAGEH + r1g * LDT + s0g * 8) * 2;

    uint32_t aB[2], bB[4];
    #pragma unroll
    for (int mt = 0; mt < 2; mt++)
        aB[mt] = smemBase +
            (uint32_t)((wm * 32 + mt * 16 + (lane & 15)) * LDT + (lane >> 4) * 8) * 2;
    #pragma unroll
    for (int nt2 = 0; nt2 < 4; nt2++)
        bB[nt2] = smemBase +
            (uint32_t)(STAGEH + (wn * 64 + nt2 * 16 + ((lane >> 3) & 1) * 8 + (lane & 7)) * LDT
                       + (lane >> 4) * 8) * 2;

    float acc[2][8][4];
    #pragma unroll
    for (int i = 0; i < 2; i++)
        #pragma unroll
        for (int j = 0; j < 8; j++)
            #pragma unroll
            for (int c = 0; c < 4; c++) acc[i][j][c] = 0.f;

    int NIT = K >> 6;                 // 64-k chunks
    ISSUE(0, 0);

    for (int i = 0; i < NIT; i++) {
        int st = i & 1;
        asm volatile("cp.async.wait_group 0;");   // chunk i arrived
        __syncthreads();                          // visible; prev compute done
        if (i + 1 < NIT)
            ISSUE(st ^ 1, (i + 1) * 64);          // overlap with compute below
        #pragma unroll
        for (int sub = 0; sub < 2; sub++) {
            uint32_t sb = (uint32_t)st * CHUNKB + (uint32_t)sub * SUBB;
            #pragma unroll
            for (int ks = 0; ks < 2; ks++) {
                uint32_t a[2][4];
                #pragma unroll
                for (int mt = 0; mt < 2; mt++)
                    LDSM4(a[mt][0], a[mt][1], a[mt][2], a[mt][3],
                          aB[mt] + sb + ks * 32);
                #pragma unroll
                for (int nt2 = 0; nt2 < 4; nt2++) {
                    uint32_t b0, b1, b2, b3;
                    LDSM4(b0, b1, b2, b3, bB[nt2] + sb + ks * 32);
                    #pragma unroll
                    for (int mt = 0; mt < 2; mt++) {
                        MMA16816(acc[mt][nt2 * 2],     a[mt][0], a[mt][1], a[mt][2], a[mt][3], b0, b2);
                        MMA16816(acc[mt][nt2 * 2 + 1], a[mt][0], a[mt][1], a[mt][2], a[mt][3], b1, b3);
                    }
                }
            }
        }
    }

    int qr = lane >> 2, qc = (lane & 3) * 2;
    #pragma unroll
    for (int nt = 0; nt < 8; nt++) {
        int col = n0 + wn * 64 + nt * 8 + qc;
        float b0 = bias[col], b1 = bias[col + 1];
        #pragma unroll
        for (int mt = 0; mt < 2; mt++) {
            int ra = m0 + wm * 32 + mt * 16 + qr;
            int rb = ra + 8;
            float v0 = acc[mt][nt][0] + b0, v1 = acc[mt][nt][1] + b1;
            float v2 = acc[mt][nt][2] + b0, v3 = acc[mt][nt][3] + b1;
            if (EPI == 1) {
                v0 = gelu_f(v0); v1 = gelu_f(v1);
                v2 = gelu_f(v2); v3 = gelu_f(v3);
            }
            if (EPI == 2) {
                const float2 ru = *(const float2*)(res + (size_t)ra * N + col);
                const float2 rl = *(const float2*)(res + (size_t)rb * N + col);
                v0 += ru.x; v1 += ru.y; v2 += rl.x; v3 += rl.y;
            }
            if (EPI == 3) {
                int sa = spatial_of(ra), sbr = spatial_of(rb);
                const float2 ru = *(const float2*)(res + (size_t)sa * N + col);
                const float2 rl = *(const float2*)(res + (size_t)sbr * N + col);
                v0 += ru.x; v1 += ru.y; v2 += rl.x; v3 += rl.y;
                *(float2*)((float*)Cout + (size_t)sa  * N + col) = make_float2(v0, v1);
                *(float2*)((float*)Cout + (size_t)sbr * N + col) = make_float2(v2, v3);
                continue;
            }
            if (sizeof(OutT) == 2) {
                *(__half2*)((__half*)Cout + (size_t)ra * N + col) = __floats2half2_rn(v0, v1);
                *(__half2*)((__half*)Cout + (size_t)rb * N + col) = __floats2half2_rn(v2, v3);
            } else {
                *(float2*)((float*)Cout + (size_t)ra * N + col) = make_float2(v0, v1);
                *(float2*)((float*)Cout + (size_t)rb * N + col) = make_float2(v2, v3);
            }
        }
    }
}

// ---------------- tensor-core windowed attention ----------------------------
// one CTA per (head, window); 8 warps x 32 query rows; direct exp (no max:
// LN'd inputs => s ~ N(0,1), overflow-free).
#define ATT_SMEM (3 * 256 * LDT * 2)

__global__ void __launch_bounds__(256) attn_mma(const __half* __restrict__ qkv,
                                                const __half* __restrict__ bp,
                                                __half* __restrict__ out)
{
    extern __shared__ __half asmem[];
    __half* Qs = asmem;
    __half* Ks = asmem + 256 * LDT;
    __half* Vs = asmem + 2 * 256 * LDT;
    __shared__ int rs[256];

    int tid = threadIdx.x, lane = tid & 31, w = tid >> 5;
    int head = blockIdx.x, b_ = blockIdx.y;

    {
        int md = tid >> 6, mh = (tid >> 3) & 7, mw = tid & 7;
        int wd = b_ >> 6, wh = (b_ >> 3) & 7, ww = b_ & 7;
        int dd = wd * 4 + md, hh = wh * 8 + mh, wp = ww * 8 + mw;
        rs[tid] = ((dd < 4) ? 0 : ((dd < 6) ? 1 : 2)) * 9
                + ((hh < 56) ? 0 : ((hh < 60) ? 1 : 2)) * 3
                + ((wp < 56) ? 0 : ((wp < 60) ? 1 : 2));
    }

    {
        const __half* src = qkv + ((size_t)(b_ * 256 + tid) * (3 * CH) + head * HDIM);
        __half2 sc2 = __float2half2_rn(0.17677669529663687f);
        __half2 qbuf[16];
        #pragma unroll
        for (int c = 0; c < 4; c++)
            *(uint4*)&qbuf[c * 4] = *(const uint4*)(src + c * 8);
        #pragma unroll
        for (int i = 0; i < 16; i++) qbuf[i] = __hmul2(qbuf[i], sc2);
        #pragma unroll
        for (int c = 0; c < 4; c++) {
            *(uint4*)(Qs + tid * LDT + c * 8) = *(uint4*)&qbuf[c * 4];
            *(uint4*)(Ks + tid * LDT + c * 8) = *(const uint4*)(src + CH     + c * 8);
            *(uint4*)(Vs + tid * LDT + c * 8) = *(const uint4*)(src + 2 * CH + c * 8);
        }
    }
    __syncthreads();

    int qr = lane >> 2, qc = (lane & 3) * 2;
    int rsq[2][2];
    #pragma unroll
    for (int mt = 0; mt < 2; mt++) {
        int r = w * 32 + mt * 16 + qr;
        rsq[mt][0] = rs[r]; rsq[mt][1] = rs[r + 8];
    }

    uint32_t smb = (uint32_t)__cvta_generic_to_shared(asmem);
    uint32_t aQ[2];
    #pragma unroll
    for (int mt = 0; mt < 2; mt++)
        aQ[mt] = smb + (uint32_t)((w * 32 + mt * 16 + (lane & 15)) * LDT
                                  + (lane >> 4) * 8) * 2;
    int krow = ((lane >> 3) & 1) * 8 + (lane & 7);
    uint32_t kb0 = smb + (uint32_t)(256 * LDT + krow * LDT + (lane >> 4) * 8) * 2;
    uint32_t vb0 = smb + (uint32_t)(2 * 256 * LDT + krow * LDT) * 2 + (lane >> 4) * 16;

    float Oacc[2][4][4];
    #pragma unroll
    for (int mt = 0; mt < 2; mt++)
        #pragma unroll
        for (int n = 0; n < 4; n++)
            #pragma unroll
            for (int e = 0; e < 4; e++) Oacc[mt][n][e] = 0.f;
    float rsum[2][2] = {{0.f, 0.f}, {0.f, 0.f}};

    for (int cb = 0; cb < 4; cb++) {
        float S[2][8][4];
        #pragma unroll
        for (int mt = 0; mt < 2; mt++)
            #pragma unroll
            for (int n = 0; n < 8; n++)
                #pragma unroll
                for (int e = 0; e < 4; e++) S[mt][n][e] = 0.f;

        #pragma unroll
        for (int ks = 0; ks < 2; ks++) {
            uint32_t a[2][4];
            #pragma unroll
            for (int mt = 0; mt < 2; mt++)
                LDSM4(a[mt][0], a[mt][1], a[mt][2], a[mt][3], aQ[mt] + ks * 32);
            #pragma unroll
            for (int nt2 = 0; nt2 < 4; nt2++) {
                uint32_t b0, b1, b2, b3;
                LDSM4(b0, b1, b2, b3,
                      kb0 + (uint32_t)(cb * 64 + nt2 * 16) * (LDT * 2) + ks * 32);
                #pragma unroll
                for (int mt = 0; mt < 2; mt++) {
                    MMA16816(S[mt][nt2 * 2],     a[mt][0], a[mt][1], a[mt][2], a[mt][3], b0, b2);
                    MMA16816(S[mt][nt2 * 2 + 1], a[mt][0], a[mt][1], a[mt][2], a[mt][3], b1, b3);
                }
            }
        }

        uint32_t P[2][8][2];
        #pragma unroll
        for (int mt = 0; mt < 2; mt++) {
            int row = w * 32 + mt * 16 + qr;
            #pragma unroll
            for (int nt = 0; nt < 8; nt++) {
                int col = cb * 64 + nt * 8 + qc;
                float2 bU = __half22float2(*(const __half2*)(bp + ((head * 256 + row)     * 256 + col)));
                float2 bL = __half22float2(*(const __half2*)(bp + ((head * 256 + row + 8) * 256 + col)));
                int2 rcc = *(const int2*)(rs + col);
                float s0 = S[mt][nt][0] + bU.x + ((rcc.x == rsq[mt][0]) ? 0.f : -100.f);
                float s1 = S[mt][nt][1] + bU.y + ((rcc.y == rsq[mt][0]) ? 0.f : -100.f);
                float s2 = S[mt][nt][2] + bL.x + ((rcc.x == rsq[mt][1]) ? 0.f : -100.f);
                float s3 = S[mt][nt][3] + bL.y + ((rcc.y == rsq[mt][1]) ? 0.f : -100.f);
                float p0 = __expf(s0), p1 = __expf(s1);
                float p2 = __expf(s2), p3 = __expf(s3);
                rsum[mt][0] += p0 + p1;
                rsum[mt][1] += p2 + p3;
                __half2 h0 = __floats2half2_rn(p0, p1);
                __half2 h1 = __floats2half2_rn(p2, p3);
                P[mt][nt][0] = *(uint32_t*)&h0;
                P[mt][nt][1] = *(uint32_t*)&h1;
            }
        }

        #pragma unroll
        for (int j = 0; j < 4; j++) {
            #pragma unroll
            for (int dh = 0; dh < 2; dh++) {
                uint32_t b0, b1, b2, b3;
                LDSM4T(b0, b1, b2, b3,
                       vb0 + (uint32_t)(cb * 64 + j * 16) * (LDT * 2) + dh * 32);
                #pragma unroll
                for (int mt = 0; mt < 2; mt++) {
                    MMA16816(Oacc[mt][dh * 2],
                             P[mt][2 * j][0], P[mt][2 * j][1],
                             P[mt][2 * j + 1][0], P[mt][2 * j + 1][1], b0, b1);
                    MMA16816(Oacc[mt][dh * 2 + 1],
                             P[mt][2 * j][0], P[mt][2 * j][1],
                             P[mt][2 * j + 1][0], P[mt][2 * j + 1][1], b2, b3);
                }
            }
        }
    }

    float inv[2][2];
    #pragma unroll
    for (int mt = 0; mt < 2; mt++)
        #pragma unroll
        for (int h = 0; h < 2; h++) {
            float v = rsum[mt][h];
            v += __shfl_xor_sync(0xFFFFFFFFu, v, 1);
            v += __shfl_xor_sync(0xFFFFFFFFu, v, 2);
            inv[mt][h] = 1.f / v;
        }
    #pragma unroll
    for (int mt = 0; mt < 2; mt++) {
        int row = b_ * 256 + w * 32 + mt * 16 + qr;
        #pragma unroll
        for (int nd = 0; nd < 4; nd++) {
            int col = head * HDIM + nd * 8 + qc;
            __half2 h0 = __floats2half2_rn(Oacc[mt][nd][0] * inv[mt][0],
                                           Oacc[mt][nd][1] * inv[mt][0]);
            __half2 h1 = __floats2half2_rn(Oacc[mt][nd][2] * inv[mt][1],
                                           Oacc[mt][nd][3] * inv[mt][1]);
            *(__half2*)(out + (size_t)row * CH + col)       = h0;
            *(__half2*)(out + (size_t)(row + 8) * CH + col) = h1;
        }
    }
}

// ---------------- launch ----------------------------------------------------
extern "C" void kernel_launch(void* const* d_in, const int* in_sizes, int n_in,
                              void* d_out, int out_size)
{
    const float* x    = (const float*)d_in[0];
    const float* n1w  = (const float*)d_in[1];
    const float* n1b  = (const float*)d_in[2];
    const float* qkvw = (const float*)d_in[3];
    const float* qkvb = (const float*)d_in[4];
    const float* rpb  = (const float*)d_in[5];
    const float* pw   = (const float*)d_in[6];
    const float* pb   = (const float*)d_in[7];
    const float* n2w  = (const float*)d_in[8];
    const float* n2b  = (const float*)d_in[9];
    const float* f1w  = (const float*)d_in[10];
    const float* f1b  = (const float*)d_in[11];
    const float* f2w  = (const float*)d_in[12];
    const float* f2b  = (const float*)d_in[13];
    float* out = (float*)d_out;

    void *pv;
    __half *hwin, *qkv, *attn, *h2, *f1, *wq, *wpw, *w1, *w2, *bp;
    float *x1;
    cudaGetSymbolAddress(&pv, g_hwin); hwin = (__half*)pv;
    cudaGetSymbolAddress(&pv, g_qkv);  qkv  = (__half*)pv;
    cudaGetSymbolAddress(&pv, g_attn); attn = (__half*)pv;
    cudaGetSymbolAddress(&pv, g_x1);   x1   = (float*)pv;
    cudaGetSymbolAddress(&pv, g_h2);   h2   = (__half*)pv;
    cudaGetSymbolAddress(&pv, g_f1);   f1   = (__half*)pv;
    cudaGetSymbolAddress(&pv, g_wq);   wq   = (__half*)pv;
    cudaGetSymbolAddress(&pv, g_wp);   wpw  = (__half*)pv;
    cudaGetSymbolAddress(&pv, g_w1);   w1   = (__half*)pv;
    cudaGetSymbolAddress(&pv, g_w2);   w2   = (__half*)pv;
    cudaGetSymbolAddress(&pv, g_bias); bp   = (__half*)pv;

    cudaFuncSetAttribute(attn_mma,
                         cudaFuncAttributeMaxDynamicSharedMemorySize, ATT_SMEM);
    cudaFuncSetAttribute(hgemm_nt<0, __half>,
                         cudaFuncAttributeMaxDynamicSharedMemorySize, SMEM_BYTES);
    cudaFuncSetAttribute(hgemm_nt<1, __half>,
                         cudaFuncAttributeMaxDynamicSharedMemorySize, SMEM_BYTES);
    cudaFuncSetAttribute(hgemm_nt<2, float>,
                         cudaFuncAttributeMaxDynamicSharedMemorySize, SMEM_BYTES);
    cudaFuncSetAttribute(hgemm_nt<3, float>,
                         cudaFuncAttributeMaxDynamicSharedMemorySize, SMEM_BYTES);

    // 0. weight conversion + bias precompute
    f2h4<<<(442368 + 255) / 256, 256>>>(qkvw, wq, pw, wpw, f1w, w1, f2w, w2);
    bias_pre<<<NHEAD * 256 * 256 / 256, 256>>>(rpb, bp);

    // 1. LN1 + shift + window partition (half out)
    ln_kernel<true><<<TOKENS / 8, 256>>>(x, n1w, n1b, hwin);
    // 2. QKV (half out)
    hgemm_nt<0, __half><<<dim3(3*CH/128, TOKENS/128), 256, SMEM_BYTES>>>(
        hwin, wq, qkvb, nullptr, qkv, TOKENS, 3*CH, CH);
    // 3. attention (tensor-core, half out)
    attn_mma<<<dim3(NHEAD, 128), 256, ATT_SMEM>>>(qkv, bp, attn);
    // 4. proj + window-reverse + unshift + residual -> x1 (float)
    hgemm_nt<3, float><<<dim3(CH/128, TOKENS/128), 256, SMEM_BYTES>>>(
        attn, wpw, pb, x, x1, TOKENS, CH, CH);
    // 5. LN2 (half out)
    ln_kernel<false><<<TOKENS / 8, 256>>>(x1, n2w, n2b, h2);
    // 6. fc1 + GELU (half out)
    hgemm_nt<1, __half><<<dim3(DFF/128, TOKENS/128), 256, SMEM_BYTES>>>(
        h2, w1, f1b, nullptr, f1, TOKENS, DFF, CH);
    // 7. fc2 + residual -> d_out (fp32)
    hgemm_nt<2, float><<<dim3(CH/128, TOKENS/128), 256, SMEM_BYTES>>>(
        f1, w2, f2b, x1, out, TOKENS, CH, DFF);
}

// round 17
// speedup vs baseline: 1.0772x; 1.0297x over previous
#include <cuda_runtime.h>
#include <cuda_fp16.h>
#include <stdint.h>
#include <math.h>

#define TOKENS 32768
#define CH     384
#define DFF    1536
#define NHEAD  12
#define HDIM   32

// ---------------- scratch ----------------------------------------------------
__device__ __half g_hwin[(size_t)TOKENS * CH];
__device__ __half g_qkv [(size_t)TOKENS * 3 * CH];
__device__ __half g_attn[(size_t)TOKENS * CH];
__device__ float  g_x1  [(size_t)TOKENS * CH];
__device__ __half g_h2  [(size_t)TOKENS * CH];
__device__ __half g_f1  [(size_t)TOKENS * DFF];
__device__ __half g_wq  [3 * CH * CH];
__device__ __half g_wp  [CH * CH];
__device__ __half g_w1  [DFF * CH];
__device__ __half g_w2  [CH * DFF];
__device__ __half g_bias[NHEAD * 256 * 256];   // precomputed rel-pos bias

// ---------------- fused fp32 -> fp16 weight conversion ----------------------
__global__ void __launch_bounds__(256) f2h4(const float* __restrict__ s0, __half* d0,
                                            const float* __restrict__ s1, __half* d1,
                                            const float* __restrict__ s2, __half* d2,
                                            const float* __restrict__ s3, __half* d3)
{
    int q = blockIdx.x * 256 + threadIdx.x;
    const float* s; __half* d; int off;
    if      (q < 110592)  { s = s0; d = d0; off = q; }
    else if (q < 147456)  { s = s1; d = d1; off = q - 110592; }
    else if (q < 294912)  { s = s2; d = d2; off = q - 147456; }
    else if (q < 442368)  { s = s3; d = d3; off = q - 294912; }
    else return;
    float4 v = ((const float4*)s)[off];
    __half2* o = (__half2*)(d + off * 4);
    o[0] = __floats2half2_rn(v.x, v.y);
    o[1] = __floats2half2_rn(v.z, v.w);
}

// ---------------- rel-pos bias precompute: bp[head][query][key] -------------
__global__ void __launch_bounds__(256) bias_pre(const float* __restrict__ rpb,
                                                __half* __restrict__ bp)
{
    int i = blockIdx.x * 256 + threadIdx.x;     // 786432 total
    int head = i >> 16, r = (i >> 8) & 255, c = i & 255;
    int fr = (r >> 6) * 225 + ((r >> 3) & 7) * 15 + (r & 7);
    int fc = (c >> 6) * 225 + ((c >> 3) & 7) * 15 + (c & 7);
    bp[i] = __float2half(rpb[(fr - fc + 787) * NHEAD + head]);
}

// ---------------- LayerNorm (+ optional shift & window partition), half out -
template<bool WIN>
__global__ void __launch_bounds__(256) ln_kernel(const float* __restrict__ x,
                                                 const float* __restrict__ w,
                                                 const float* __restrict__ bb,
                                                 __half* __restrict__ out)
{
    int gw   = (blockIdx.x * blockDim.x + threadIdx.x) >> 5;
    int lane = threadIdx.x & 31;
    size_t src;
    if (WIN) {
        int b_ = gw >> 8, n = gw & 255;
        int wd = b_ >> 6, wh = (b_ >> 3) & 7, ww = b_ & 7;
        int id = n >> 6,  ih = (n >> 3) & 7,  iw = n & 7;
        int sd = (wd * 4 + id + 2) & 7;
        int sh = (wh * 8 + ih + 4) & 63;
        int sw = (ww * 8 + iw + 4) & 63;
        src = (size_t)(((sd << 6) + sh) * 64 + sw) * CH;
    } else {
        src = (size_t)gw * CH;
    }
    const float4* xp = (const float4*)(x + src);
    float4 v0 = xp[lane], v1 = xp[lane + 32], v2 = xp[lane + 64];
    float s  = v0.x + v0.y + v0.z + v0.w + v1.x + v1.y + v1.z + v1.w
             + v2.x + v2.y + v2.z + v2.w;
    float s2 = v0.x*v0.x + v0.y*v0.y + v0.z*v0.z + v0.w*v0.w
             + v1.x*v1.x + v1.y*v1.y + v1.z*v1.z + v1.w*v1.w
             + v2.x*v2.x + v2.y*v2.y + v2.z*v2.z + v2.w*v2.w;
    #pragma unroll
    for (int o = 16; o; o >>= 1) {
        s  += __shfl_xor_sync(0xFFFFFFFFu, s,  o);
        s2 += __shfl_xor_sync(0xFFFFFFFFu, s2, o);
    }
    float mu  = s * (1.f / CH);
    float var = s2 * (1.f / CH) - mu * mu;
    float rsv = rsqrtf(var + 1e-5f);

    __half2* op = (__half2*)(out + (size_t)gw * CH);
    const float4* wp = (const float4*)w;
    const float4* bp = (const float4*)bb;
    float4 vv[3] = {v0, v1, v2};
    #pragma unroll
    for (int i = 0; i < 3; i++) {
        float4 wv = wp[lane + 32 * i];
        float4 bv = bp[lane + 32 * i];
        float rx = (vv[i].x - mu) * rsv * wv.x + bv.x;
        float ry = (vv[i].y - mu) * rsv * wv.y + bv.y;
        float rz = (vv[i].z - mu) * rsv * wv.z + bv.z;
        float rw = (vv[i].w - mu) * rsv * wv.w + bv.w;
        op[64 * i + 2 * lane]     = __floats2half2_rn(rx, ry);
        op[64 * i + 2 * lane + 1] = __floats2half2_rn(rz, rw);
    }
}

// windowed token -> spatial token (reverse shift + window reverse)
__device__ __forceinline__ int spatial_of(int t) {
    int b_ = t >> 8, n = t & 255;
    int A = (((b_ >> 6)       * 4) + (n >> 6)       + 2) & 7;
    int B = ((((b_ >> 3) & 7) * 8) + ((n >> 3) & 7) + 4) & 63;
    int Cc = (((b_ & 7)       * 8) + (n & 7)        + 4) & 63;
    return ((A << 6) + B) * 64 + Cc;
}

// ---------------- mma/ldmatrix macros ----------------------------------------
#define LDSM4(r0,r1,r2,r3,addr) \
    asm volatile("ldmatrix.sync.aligned.m8n8.x4.shared.b16 {%0,%1,%2,%3}, [%4];" \
        : "=r"(r0), "=r"(r1), "=r"(r2), "=r"(r3) : "r"(addr))

#define LDSM4T(r0,r1,r2,r3,addr) \
    asm volatile("ldmatrix.sync.aligned.m8n8.x4.trans.shared.b16 {%0,%1,%2,%3}, [%4];" \
        : "=r"(r0), "=r"(r1), "=r"(r2), "=r"(r3) : "r"(addr))

#define MMA16816(d,a0,a1,a2,a3,b0,b1) \
    asm volatile("mma.sync.aligned.m16n8k16.row.col.f32.f16.f16.f32 " \
        "{%0,%1,%2,%3}, {%4,%5,%6,%7}, {%8,%9}, {%0,%1,%2,%3};" \
        : "+f"(d[0]), "+f"(d[1]), "+f"(d[2]), "+f"(d[3]) \
        : "r"(a0), "r"(a1), "r"(a2), "r"(a3), "r"(b0), "r"(b1))

#define CPA16(dst, src) \
    asm volatile("cp.async.cg.shared.global [%0], [%1], 16;" :: "r"(dst), "l"(src))

// ---------------- fp16 tensor-core GEMM, K-chunk 64, 2-stage pipeline -------
#define LDT     40
#define STAGEH  (128 * LDT)
#define SUBB    (STAGEH * 2 * 2)     // bytes per 32-k sub-tile (A+B) = 20480
#define CHUNKB  (2 * SUBB)           // bytes per 64-k stage = 40960
#define NSTAGE  2
#define SMEM_BYTES (NSTAGE * CHUNKB) // 81920

__device__ __forceinline__ float gelu_f(float v) {
    return 0.5f * v * (1.f + erff(v * 0.70710678118654752f));
}

#define ISSUE(st, k0) do { \
    uint32_t d_ = smemBase + (uint32_t)(st) * CHUNKB; \
    CPA16(d_ + offA0,        Ap0 + (k0)); \
    CPA16(d_ + offA1,        Ap1 + (k0)); \
    CPA16(d_ + offB0,        Bp0 + (k0)); \
    CPA16(d_ + offB1,        Bp1 + (k0)); \
    CPA16(d_ + SUBB + offA0, Ap0 + (k0) + 32); \
    CPA16(d_ + SUBB + offA1, Ap1 + (k0) + 32); \
    CPA16(d_ + SUBB + offB0, Bp0 + (k0) + 32); \
    CPA16(d_ + SUBB + offB1, Bp1 + (k0) + 32); \
    asm volatile("cp.async.commit_group;"); \
} while (0)

template<int EPI, typename OutT>
__global__ void __launch_bounds__(256) hgemm_nt(const __half* __restrict__ A,
                                                const __half* __restrict__ B,
                                                const float* __restrict__ bias,
                                                const float* __restrict__ res,
                                                OutT* __restrict__ Cout,
                                                int M, int N, int K)
{
    extern __shared__ __half smp[];
    int tid  = threadIdx.x;
    int lane = tid & 31;
    int wid  = tid >> 5;
    int wm   = wid & 3;
    int wn   = wid >> 2;
    int m0 = blockIdx.y * 128, n0 = blockIdx.x * 128;

    int r0g = tid >> 2, s0g = tid & 3;
    int r1g = (tid + 256) >> 2;
    const __half* Ap0 = A + (size_t)(m0 + r0g) * K + s0g * 8;
    const __half* Ap1 = A + (size_t)(m0 + r1g) * K + s0g * 8;
    const __half* Bp0 = B + (size_t)(n0 + r0g) * K + s0g * 8;
    const __half* Bp1 = B + (size_t)(n0 + r1g) * K + s0g * 8;

    uint32_t smemBase = (uint32_t)__cvta_generic_to_shared(smp);
    uint32_t offA0 = (uint32_t)(r0g * LDT + s0g * 8) * 2;
    uint32_t offA1 = (uint32_t)(r1g * LDT + s0g * 8) * 2;
    uint32_t offB0 = (uint32_t)(STAGEH + r0g * LDT + s0g * 8) * 2;
    uint32_t offB1 = (uint32_t)(STAGEH + r1g * LDT + s0g * 8) * 2;

    uint32_t aB[2], bB[4];
    #pragma unroll
    for (int mt = 0; mt < 2; mt++)
        aB[mt] = smemBase +
            (uint32_t)((wm * 32 + mt * 16 + (lane & 15)) * LDT + (lane >> 4) * 8) * 2;
    #pragma unroll
    for (int nt2 = 0; nt2 < 4; nt2++)
        bB[nt2] = smemBase +
            (uint32_t)(STAGEH + (wn * 64 + nt2 * 16 + ((lane >> 3) & 1) * 8 + (lane & 7)) * LDT
                       + (lane >> 4) * 8) * 2;

    float acc[2][8][4];
    #pragma unroll
    for (int i = 0; i < 2; i++)
        #pragma unroll
        for (int j = 0; j < 8; j++)
            #pragma unroll
            for (int c = 0; c < 4; c++) acc[i][j][c] = 0.f;

    int NIT = K >> 6;
    ISSUE(0, 0);

    for (int i = 0; i < NIT; i++) {
        int st = i & 1;
        asm volatile("cp.async.wait_group 0;");
        __syncthreads();
        if (i + 1 < NIT)
            ISSUE(st ^ 1, (i + 1) * 64);
        #pragma unroll
        for (int sub = 0; sub < 2; sub++) {
            uint32_t sb = (uint32_t)st * CHUNKB + (uint32_t)sub * SUBB;
            #pragma unroll
            for (int ks = 0; ks < 2; ks++) {
                uint32_t a[2][4];
                #pragma unroll
                for (int mt = 0; mt < 2; mt++)
                    LDSM4(a[mt][0], a[mt][1], a[mt][2], a[mt][3],
                          aB[mt] + sb + ks * 32);
                #pragma unroll
                for (int nt2 = 0; nt2 < 4; nt2++) {
                    uint32_t b0, b1, b2, b3;
                    LDSM4(b0, b1, b2, b3, bB[nt2] + sb + ks * 32);
                    #pragma unroll
                    for (int mt = 0; mt < 2; mt++) {
                        MMA16816(acc[mt][nt2 * 2],     a[mt][0], a[mt][1], a[mt][2], a[mt][3], b0, b2);
                        MMA16816(acc[mt][nt2 * 2 + 1], a[mt][0], a[mt][1], a[mt][2], a[mt][3], b1, b3);
                    }
                }
            }
        }
    }

    int qr = lane >> 2, qc = (lane & 3) * 2;
    #pragma unroll
    for (int nt = 0; nt < 8; nt++) {
        int col = n0 + wn * 64 + nt * 8 + qc;
        float b0 = bias[col], b1 = bias[col + 1];
        #pragma unroll
        for (int mt = 0; mt < 2; mt++) {
            int ra = m0 + wm * 32 + mt * 16 + qr;
            int rb = ra + 8;
            float v0 = acc[mt][nt][0] + b0, v1 = acc[mt][nt][1] + b1;
            float v2 = acc[mt][nt][2] + b0, v3 = acc[mt][nt][3] + b1;
            if (EPI == 1) {
                v0 = gelu_f(v0); v1 = gelu_f(v1);
                v2 = gelu_f(v2); v3 = gelu_f(v3);
            }
            if (EPI == 2) {
                const float2 ru = *(const float2*)(res + (size_t)ra * N + col);
                const float2 rl = *(const float2*)(res + (size_t)rb * N + col);
                v0 += ru.x; v1 += ru.y; v2 += rl.x; v3 += rl.y;
            }
            if (EPI == 3) {
                int sa = spatial_of(ra), sbr = spatial_of(rb);
                const float2 ru = *(const float2*)(res + (size_t)sa * N + col);
                const float2 rl = *(const float2*)(res + (size_t)sbr * N + col);
                v0 += ru.x; v1 += ru.y; v2 += rl.x; v3 += rl.y;
                *(float2*)((float*)Cout + (size_t)sa  * N + col) = make_float2(v0, v1);
                *(float2*)((float*)Cout + (size_t)sbr * N + col) = make_float2(v2, v3);
                continue;
            }
            if (sizeof(OutT) == 2) {
                *(__half2*)((__half*)Cout + (size_t)ra * N + col) = __floats2half2_rn(v0, v1);
                *(__half2*)((__half*)Cout + (size_t)rb * N + col) = __floats2half2_rn(v2, v3);
            } else {
                *(float2*)((float*)Cout + (size_t)ra * N + col) = make_float2(v0, v1);
                *(float2*)((float*)Cout + (size_t)rb * N + col) = make_float2(v2, v3);
            }
        }
    }
}

// ---------------- tensor-core windowed attention (32-col key blocks) --------
// one CTA per (head, window); 8 warps x 32 query rows; keys processed in
// 8 blocks of 32 to shrink live registers -> 2 CTAs/SM.
#define ATT_SMEM (3 * 256 * LDT * 2)

__global__ void __launch_bounds__(256, 2) attn_mma(const __half* __restrict__ qkv,
                                                   const __half* __restrict__ bp,
                                                   __half* __restrict__ out)
{
    extern __shared__ __half asmem[];
    __half* Qs = asmem;
    __half* Ks = asmem + 256 * LDT;
    __half* Vs = asmem + 2 * 256 * LDT;
    __shared__ int rs[256];

    int tid = threadIdx.x, lane = tid & 31, w = tid >> 5;
    int head = blockIdx.x, b_ = blockIdx.y;

    {
        int md = tid >> 6, mh = (tid >> 3) & 7, mw = tid & 7;
        int wd = b_ >> 6, wh = (b_ >> 3) & 7, ww = b_ & 7;
        int dd = wd * 4 + md, hh = wh * 8 + mh, wp = ww * 8 + mw;
        rs[tid] = ((dd < 4) ? 0 : ((dd < 6) ? 1 : 2)) * 9
                + ((hh < 56) ? 0 : ((hh < 60) ? 1 : 2)) * 3
                + ((wp < 56) ? 0 : ((wp < 60) ? 1 : 2));
    }

    {
        const __half* src = qkv + ((size_t)(b_ * 256 + tid) * (3 * CH) + head * HDIM);
        __half2 sc2 = __float2half2_rn(0.17677669529663687f);
        __half2 qbuf[16];
        #pragma unroll
        for (int c = 0; c < 4; c++)
            *(uint4*)&qbuf[c * 4] = *(const uint4*)(src + c * 8);
        #pragma unroll
        for (int i = 0; i < 16; i++) qbuf[i] = __hmul2(qbuf[i], sc2);
        #pragma unroll
        for (int c = 0; c < 4; c++) {
            *(uint4*)(Qs + tid * LDT + c * 8) = *(uint4*)&qbuf[c * 4];
            *(uint4*)(Ks + tid * LDT + c * 8) = *(const uint4*)(src + CH     + c * 8);
            *(uint4*)(Vs + tid * LDT + c * 8) = *(const uint4*)(src + 2 * CH + c * 8);
        }
    }
    __syncthreads();

    int qr = lane >> 2, qc = (lane & 3) * 2;
    int rsq[2][2];
    #pragma unroll
    for (int mt = 0; mt < 2; mt++) {
        int r = w * 32 + mt * 16 + qr;
        rsq[mt][0] = rs[r]; rsq[mt][1] = rs[r + 8];
    }

    uint32_t smb = (uint32_t)__cvta_generic_to_shared(asmem);
    uint32_t aQ[2];
    #pragma unroll
    for (int mt = 0; mt < 2; mt++)
        aQ[mt] = smb + (uint32_t)((w * 32 + mt * 16 + (lane & 15)) * LDT
                                  + (lane >> 4) * 8) * 2;
    int krow = ((lane >> 3) & 1) * 8 + (lane & 7);
    uint32_t kb0 = smb + (uint32_t)(256 * LDT + krow * LDT + (lane >> 4) * 8) * 2;
    uint32_t vb0 = smb + (uint32_t)(2 * 256 * LDT + krow * LDT) * 2 + (lane >> 4) * 16;

    float Oacc[2][4][4];
    #pragma unroll
    for (int mt = 0; mt < 2; mt++)
        #pragma unroll
        for (int n = 0; n < 4; n++)
            #pragma unroll
            for (int e = 0; e < 4; e++) Oacc[mt][n][e] = 0.f;
    float rsum[2][2] = {{0.f, 0.f}, {0.f, 0.f}};

    for (int cb = 0; cb < 8; cb++) {          // 32-key blocks
        float S[2][4][4];
        #pragma unroll
        for (int mt = 0; mt < 2; mt++)
            #pragma unroll
            for (int n = 0; n < 4; n++)
                #pragma unroll
                for (int e = 0; e < 4; e++) S[mt][n][e] = 0.f;

        #pragma unroll
        for (int ks = 0; ks < 2; ks++) {
            uint32_t a[2][4];
            #pragma unroll
            for (int mt = 0; mt < 2; mt++)
                LDSM4(a[mt][0], a[mt][1], a[mt][2], a[mt][3], aQ[mt] + ks * 32);
            #pragma unroll
            for (int nt2 = 0; nt2 < 2; nt2++) {
                uint32_t b0, b1, b2, b3;
                LDSM4(b0, b1, b2, b3,
                      kb0 + (uint32_t)(cb * 32 + nt2 * 16) * (LDT * 2) + ks * 32);
                #pragma unroll
                for (int mt = 0; mt < 2; mt++) {
                    MMA16816(S[mt][nt2 * 2],     a[mt][0], a[mt][1], a[mt][2], a[mt][3], b0, b2);
                    MMA16816(S[mt][nt2 * 2 + 1], a[mt][0], a[mt][1], a[mt][2], a[mt][3], b1, b3);
                }
            }
        }

        // bias + mask + exp -> P fragments
        uint32_t P[2][4][2];
        #pragma unroll
        for (int mt = 0; mt < 2; mt++) {
            int row = w * 32 + mt * 16 + qr;
            #pragma unroll
            for (int nt = 0; nt < 4; nt++) {
                int col = cb * 32 + nt * 8 + qc;
                float2 bU = __half22float2(*(const __half2*)(bp + ((head * 256 + row)     * 256 + col)));
                float2 bL = __half22float2(*(const __half2*)(bp + ((head * 256 + row + 8) * 256 + col)));
                int2 rcc = *(const int2*)(rs + col);
                float s0 = S[mt][nt][0] + bU.x + ((rcc.x == rsq[mt][0]) ? 0.f : -100.f);
                float s1 = S[mt][nt][1] + bU.y + ((rcc.y == rsq[mt][0]) ? 0.f : -100.f);
                float s2 = S[mt][nt][2] + bL.x + ((rcc.x == rsq[mt][1]) ? 0.f : -100.f);
                float s3 = S[mt][nt][3] + bL.y + ((rcc.y == rsq[mt][1]) ? 0.f : -100.f);
                float p0 = __expf(s0), p1 = __expf(s1);
                float p2 = __expf(s2), p3 = __expf(s3);
                rsum[mt][0] += p0 + p1;
                rsum[mt][1] += p2 + p3;
                __half2 h0 = __floats2half2_rn(p0, p1);
                __half2 h1 = __floats2half2_rn(p2, p3);
                P[mt][nt][0] = *(uint32_t*)&h0;
                P[mt][nt][1] = *(uint32_t*)&h1;
            }
        }

        // O += P @ V (keys cb*32 .. cb*32+31)
        #pragma unroll
        for (int j = 0; j < 2; j++) {
            #pragma unroll
            for (int dh = 0; dh < 2; dh++) {
                uint32_t b0, b1, b2, b3;
                LDSM4T(b0, b1, b2, b3,
                       vb0 + (uint32_t)(cb * 32 + j * 16) * (LDT * 2) + dh * 32);
                #pragma unroll
                for (int mt = 0; mt < 2; mt++) {
                    MMA16816(Oacc[mt][dh * 2],
                             P[mt][2 * j][0], P[mt][2 * j][1],
                             P[mt][2 * j + 1][0], P[mt][2 * j + 1][1], b0, b1);
                    MMA16816(Oacc[mt][dh * 2 + 1],
                             P[mt][2 * j][0], P[mt][2 * j][1],
                             P[mt][2 * j + 1][0], P[mt][2 * j + 1][1], b2, b3);
                }
            }
        }
    }

    float inv[2][2];
    #pragma unroll
    for (int mt = 0; mt < 2; mt++)
        #pragma unroll
        for (int h = 0; h < 2; h++) {
            float v = rsum[mt][h];
            v += __shfl_xor_sync(0xFFFFFFFFu, v, 1);
            v += __shfl_xor_sync(0xFFFFFFFFu, v, 2);
            inv[mt][h] = 1.f / v;
        }
    #pragma unroll
    for (int mt = 0; mt < 2; mt++) {
        int row = b_ * 256 + w * 32 + mt * 16 + qr;
        #pragma unroll
        for (int nd = 0; nd < 4; nd++) {
            int col = head * HDIM + nd * 8 + qc;
            __half2 h0 = __floats2half2_rn(Oacc[mt][nd][0] * inv[mt][0],
                                           Oacc[mt][nd][1] * inv[mt][0]);
            __half2 h1 = __floats2half2_rn(Oacc[mt][nd][2] * inv[mt][1],
                                           Oacc[mt][nd][3] * inv[mt][1]);
            *(__half2*)(out + (size_t)row * CH + col)       = h0;
            *(__half2*)(out + (size_t)(row + 8) * CH + col) = h1;
        }
    }
}

// ---------------- launch ----------------------------------------------------
extern "C" void kernel_launch(void* const* d_in, const int* in_sizes, int n_in,
                              void* d_out, int out_size)
{
    const float* x    = (const float*)d_in[0];
    const float* n1w  = (const float*)d_in[1];
    const float* n1b  = (const float*)d_in[2];
    const float* qkvw = (const float*)d_in[3];
    const float* qkvb = (const float*)d_in[4];
    const float* rpb  = (const float*)d_in[5];
    const float* pw   = (const float*)d_in[6];
    const float* pb   = (const float*)d_in[7];
    const float* n2w  = (const float*)d_in[8];
    const float* n2b  = (const float*)d_in[9];
    const float* f1w  = (const float*)d_in[10];
    const float* f1b  = (const float*)d_in[11];
    const float* f2w  = (const float*)d_in[12];
    const float* f2b  = (const float*)d_in[13];
    float* out = (float*)d_out;

    void *pv;
    __half *hwin, *qkv, *attn, *h2, *f1, *wq, *wpw, *w1, *w2, *bp;
    float *x1;
    cudaGetSymbolAddress(&pv, g_hwin); hwin = (__half*)pv;
    cudaGetSymbolAddress(&pv, g_qkv);  qkv  = (__half*)pv;
    cudaGetSymbolAddress(&pv, g_attn); attn = (__half*)pv;
    cudaGetSymbolAddress(&pv, g_x1);   x1   = (float*)pv;
    cudaGetSymbolAddress(&pv, g_h2);   h2   = (__half*)pv;
    cudaGetSymbolAddress(&pv, g_f1);   f1   = (__half*)pv;
    cudaGetSymbolAddress(&pv, g_wq);   wq   = (__half*)pv;
    cudaGetSymbolAddress(&pv, g_wp);   wpw  = (__half*)pv;
    cudaGetSymbolAddress(&pv, g_w1);   w1   = (__half*)pv;
    cudaGetSymbolAddress(&pv, g_w2);   w2   = (__half*)pv;
    cudaGetSymbolAddress(&pv, g_bias); bp   = (__half*)pv;

    cudaFuncSetAttribute(attn_mma,
                         cudaFuncAttributeMaxDynamicSharedMemorySize, ATT_SMEM);
    cudaFuncSetAttribute(hgemm_nt<0, __half>,
                         cudaFuncAttributeMaxDynamicSharedMemorySize, SMEM_BYTES);
    cudaFuncSetAttribute(hgemm_nt<1, __half>,
                         cudaFuncAttributeMaxDynamicSharedMemorySize, SMEM_BYTES);
    cudaFuncSetAttribute(hgemm_nt<2, float>,
                         cudaFuncAttributeMaxDynamicSharedMemorySize, SMEM_BYTES);
    cudaFuncSetAttribute(hgemm_nt<3, float>,
                         cudaFuncAttributeMaxDynamicSharedMemorySize, SMEM_BYTES);

    // 0. weight conversion + bias precompute
    f2h4<<<(442368 + 255) / 256, 256>>>(qkvw, wq, pw, wpw, f1w, w1, f2w, w2);
    bias_pre<<<NHEAD * 256 * 256 / 256, 256>>>(rpb, bp);

    // 1. LN1 + shift + window partition (half out)
    ln_kernel<true><<<TOKENS / 8, 256>>>(x, n1w, n1b, hwin);
    // 2. QKV (half out)
    hgemm_nt<0, __half><<<dim3(3*CH/128, TOKENS/128), 256, SMEM_BYTES>>>(
        hwin, wq, qkvb, nullptr, qkv, TOKENS, 3*CH, CH);
    // 3. attention (tensor-core, half out)
    attn_mma<<<dim3(NHEAD, 128), 256, ATT_SMEM>>>(qkv, bp, attn);
    // 4. proj + window-reverse + unshift + residual -> x1 (float)
    hgemm_nt<3, float><<<dim3(CH/128, TOKENS/128), 256, SMEM_BYTES>>>(
        attn, wpw, pb, x, x1, TOKENS, CH, CH);
    // 5. LN2 (half out)
    ln_kernel<false><<<TOKENS / 8, 256>>>(x1, n2w, n2b, h2);
    // 6. fc1 + GELU (half out)
    hgemm_nt<1, __half><<<dim3(DFF/128, TOKENS/128), 256, SMEM_BYTES>>>(
        h2, w1, f1b, nullptr, f1, TOKENS, DFF, CH);
    // 7. fc2 + residual -> d_out (fp32)
    hgemm_nt<2, float><<<dim3(CH/128, TOKENS/128), 256, SMEM_BYTES>>>(
        f1, w2, f2b, x1, out, TOKENS, CH, DFF);
}